// round 9
// baseline (speedup 1.0000x reference)
#include <cuda_runtime.h>

// Inv1x1ConvPermute: kernel matrix is a permutation matrix -> pure channel gather.
// out[b,t,o] = x[b,t, g_src[o]]. DRAM-bound: 512 MiB traffic.
//
// Fused single kernel, v3. Sync-cost history:
//   R4: per-warp MEMBAR.ALL.GPU -> drained in-flight streams, -26% DRAM. FAIL.
//   R6: per-warp ld.acquire.gpu -> ~250cyc issue-block in EVERY warp, -9% DRAM. WASH.
//   R7: ONE acquire-poll per block (tid 0) + __syncthreads to broadcast the
//       ordering; hot path has zero strong ops. Poll is pass-through for all
//       blocks after wave 1.

#define C 256
#define NBUILD 64
#define WARPS_PER_BLOCK 8
#define ROWS_PER_WARP 2
#define ROWS_PER_BLOCK (WARPS_PER_BLOCK * ROWS_PER_WARP)   // 16

__device__ int g_src[C];   // g_src[o] = input channel feeding output channel o
__device__ int g_done;     // monotone build counter (accumulates across replays)

__global__ __launch_bounds__(256) void permute_fused_kernel(const float* __restrict__ x,
                                                            const float* __restrict__ kmat,
                                                            float* __restrict__ out) {
    __shared__ float s[ROWS_PER_BLOCK][C];

    int tid  = threadIdx.x;
    int bid  = blockIdx.x;
    int w    = tid >> 5;
    int lane = tid & 31;

    // ---- Phase 1: blocks 0..63 build the inverse permutation ----
    if (bid < NBUILD) {
        int e = bid * 256 + tid;            // float4 index over kmat
        int i = e >> 6;                     // kmat row (input channel)
        int c = (e & 63) * 4;               // first column of this float4
        float4 v = reinterpret_cast<const float4*>(kmat)[e];
        if (v.x != 0.0f) g_src[c + 0] = i;
        if (v.y != 0.0f) g_src[c + 1] = i;
        if (v.z != 0.0f) g_src[c + 2] = i;
        if (v.w != 0.0f) g_src[c + 3] = i;
        __threadfence();                    // publish g_src stores at gpu scope
        __syncthreads();
        if (tid == 0) atomicAdd(&g_done, 1);
    }

    // ---- Block-entry sync: ONE strong load per block, broadcast via BAR ----
    if (tid == 0) {
        int done;
        asm volatile("ld.acquire.gpu.global.b32 %0, [%1];"
                     : "=r"(done) : "l"(&g_done) : "memory");
        while (done < NBUILD) {
            __nanosleep(64);
            asm volatile("ld.acquire.gpu.global.b32 %0, [%1];"
                         : "=r"(done) : "l"(&g_done) : "memory");
        }
    }
    __syncthreads();   // block-wide fence: orders everyone's loads after the acquire

    // ---- Phase 2: R5's warp-autonomous gather, 2 rows/warp, zero strong ops ----
    long long row0 = ((long long)bid * WARPS_PER_BLOCK + w) * ROWS_PER_WARP;

    // Per-lane source indices, plain L1-cacheable loads (first touch per SM is
    // post-acquire; L1 is flushed per launch, so fills come from current L2).
    int4 src0 = reinterpret_cast<const int4*>(g_src)[lane];
    int4 src1 = reinterpret_cast<const int4*>(g_src)[lane + 32];

    // Front-batched streaming loads: 4 independent float4 (MLP=4).
    const float4* xin = reinterpret_cast<const float4*>(x + row0 * C);
    float4 v00 = __ldcs(&xin[lane]);
    float4 v01 = __ldcs(&xin[lane + 32]);
    float4 v10 = __ldcs(&xin[lane + 64]);
    float4 v11 = __ldcs(&xin[lane + 96]);

    float* r0 = s[w * ROWS_PER_WARP + 0];
    float* r1 = s[w * ROWS_PER_WARP + 1];
    *reinterpret_cast<float4*>(&r0[lane * 4])        = v00;
    *reinterpret_cast<float4*>(&r0[(lane + 32) * 4]) = v01;
    *reinterpret_cast<float4*>(&r1[lane * 4])        = v10;
    *reinterpret_cast<float4*>(&r1[(lane + 32) * 4]) = v11;
    __syncwarp();

    // Gather through shared + coalesced streaming stores.
    float4* oout = reinterpret_cast<float4*>(out + row0 * C);
    float4 o00, o01, o10, o11;
    o00.x = r0[src0.x]; o00.y = r0[src0.y]; o00.z = r0[src0.z]; o00.w = r0[src0.w];
    o01.x = r0[src1.x]; o01.y = r0[src1.y]; o01.z = r0[src1.z]; o01.w = r0[src1.w];
    o10.x = r1[src0.x]; o10.y = r1[src0.y]; o10.z = r1[src0.z]; o10.w = r1[src0.w];
    o11.x = r1[src1.x]; o11.y = r1[src1.y]; o11.z = r1[src1.z]; o11.w = r1[src1.w];
    __stcs(&oout[lane],      o00);
    __stcs(&oout[lane + 32], o01);
    __stcs(&oout[lane + 64], o10);
    __stcs(&oout[lane + 96], o11);
}

extern "C" void kernel_launch(void* const* d_in, const int* in_sizes, int n_in,
                              void* d_out, int out_size) {
    const float* x    = (const float*)d_in[0];   // [16,16384,256]
    const float* kmat = (const float*)d_in[1];   // [256,256] permutation matrix
    float* out        = (float*)d_out;

    long long total = (long long)in_sizes[0];    // B*T*C
    int nrows = (int)(total / C);                // 262144
    int grid  = nrows / ROWS_PER_BLOCK;          // 16384

    permute_fused_kernel<<<grid, 256>>>(x, kmat, out);
}

// round 10
// speedup vs baseline: 1.0023x; 1.0023x over previous
#include <cuda_runtime.h>

// Inv1x1ConvPermute: kernel matrix is a permutation matrix -> pure channel gather.
// out[b,t,o] = x[b,t, g_src[o]]. DRAM-bound: 512 MiB traffic.
//
// Fused single kernel, v3. Sync-cost history:
//   R4: per-warp MEMBAR.ALL.GPU -> drained in-flight streams, -26% DRAM. FAIL.
//   R6: per-warp ld.acquire.gpu -> ~250cyc issue-block in EVERY warp, -9% DRAM. WASH.
//   R7: ONE acquire-poll per block (tid 0) + __syncthreads to broadcast the
//       ordering; hot path has zero strong ops. Poll is pass-through for all
//       blocks after wave 1.

#define C 256
#define NBUILD 64
#define WARPS_PER_BLOCK 8
#define ROWS_PER_WARP 2
#define ROWS_PER_BLOCK (WARPS_PER_BLOCK * ROWS_PER_WARP)   // 16

__device__ int g_src[C];   // g_src[o] = input channel feeding output channel o
__device__ int g_done;     // monotone build counter (accumulates across replays)

__global__ __launch_bounds__(256) void permute_fused_kernel(const float* __restrict__ x,
                                                            const float* __restrict__ kmat,
                                                            float* __restrict__ out) {
    __shared__ float s[ROWS_PER_BLOCK][C];

    int tid  = threadIdx.x;
    int bid  = blockIdx.x;
    int w    = tid >> 5;
    int lane = tid & 31;

    // ---- Phase 1: blocks 0..63 build the inverse permutation ----
    if (bid < NBUILD) {
        int e = bid * 256 + tid;            // float4 index over kmat
        int i = e >> 6;                     // kmat row (input channel)
        int c = (e & 63) * 4;               // first column of this float4
        float4 v = reinterpret_cast<const float4*>(kmat)[e];
        if (v.x != 0.0f) g_src[c + 0] = i;
        if (v.y != 0.0f) g_src[c + 1] = i;
        if (v.z != 0.0f) g_src[c + 2] = i;
        if (v.w != 0.0f) g_src[c + 3] = i;
        __threadfence();                    // publish g_src stores at gpu scope
        __syncthreads();
        if (tid == 0) atomicAdd(&g_done, 1);
    }

    // ---- Block-entry sync: ONE strong load per block, broadcast via BAR ----
    if (tid == 0) {
        int done;
        asm volatile("ld.acquire.gpu.global.b32 %0, [%1];"
                     : "=r"(done) : "l"(&g_done) : "memory");
        while (done < NBUILD) {
            __nanosleep(64);
            asm volatile("ld.acquire.gpu.global.b32 %0, [%1];"
                         : "=r"(done) : "l"(&g_done) : "memory");
        }
    }
    __syncthreads();   // block-wide fence: orders everyone's loads after the acquire

    // ---- Phase 2: R5's warp-autonomous gather, 2 rows/warp, zero strong ops ----
    long long row0 = ((long long)bid * WARPS_PER_BLOCK + w) * ROWS_PER_WARP;

    // Per-lane source indices, plain L1-cacheable loads (first touch per SM is
    // post-acquire; L1 is flushed per launch, so fills come from current L2).
    int4 src0 = reinterpret_cast<const int4*>(g_src)[lane];
    int4 src1 = reinterpret_cast<const int4*>(g_src)[lane + 32];

    // Front-batched streaming loads: 4 independent float4 (MLP=4).
    const float4* xin = reinterpret_cast<const float4*>(x + row0 * C);
    float4 v00 = __ldcs(&xin[lane]);
    float4 v01 = __ldcs(&xin[lane + 32]);
    float4 v10 = __ldcs(&xin[lane + 64]);
    float4 v11 = __ldcs(&xin[lane + 96]);

    float* r0 = s[w * ROWS_PER_WARP + 0];
    float* r1 = s[w * ROWS_PER_WARP + 1];
    *reinterpret_cast<float4*>(&r0[lane * 4])        = v00;
    *reinterpret_cast<float4*>(&r0[(lane + 32) * 4]) = v01;
    *reinterpret_cast<float4*>(&r1[lane * 4])        = v10;
    *reinterpret_cast<float4*>(&r1[(lane + 32) * 4]) = v11;
    __syncwarp();

    // Gather through shared + coalesced streaming stores.
    float4* oout = reinterpret_cast<float4*>(out + row0 * C);
    float4 o00, o01, o10, o11;
    o00.x = r0[src0.x]; o00.y = r0[src0.y]; o00.z = r0[src0.z]; o00.w = r0[src0.w];
    o01.x = r0[src1.x]; o01.y = r0[src1.y]; o01.z = r0[src1.z]; o01.w = r0[src1.w];
    o10.x = r1[src0.x]; o10.y = r1[src0.y]; o10.z = r1[src0.z]; o10.w = r1[src0.w];
    o11.x = r1[src1.x]; o11.y = r1[src1.y]; o11.z = r1[src1.z]; o11.w = r1[src1.w];
    __stcs(&oout[lane],      o00);
    __stcs(&oout[lane + 32], o01);
    __stcs(&oout[lane + 64], o10);
    __stcs(&oout[lane + 96], o11);
}

extern "C" void kernel_launch(void* const* d_in, const int* in_sizes, int n_in,
                              void* d_out, int out_size) {
    const float* x    = (const float*)d_in[0];   // [16,16384,256]
    const float* kmat = (const float*)d_in[1];   // [256,256] permutation matrix
    float* out        = (float*)d_out;

    long long total = (long long)in_sizes[0];    // B*T*C
    int nrows = (int)(total / C);                // 262144
    int grid  = nrows / ROWS_PER_BLOCK;          // 16384

    permute_fused_kernel<<<grid, 256>>>(x, kmat, out);
}